// round 8
// baseline (speedup 1.0000x reference)
#include <cuda_runtime.h>

// 2-layer LSTM (B=2048, T=1000, I=13, H=32) + Linear(32)->ReLU->Linear(3).
// 148 blocks x 256 threads. Block = two independent 7-batch halves.
// Half = L0 GEMM group (64 thr, layer-0 rows) + L1 GEMM group (64 thr,
// layer-1 rows, pipelined one step behind), weights register-resident as
// f32x2 k-pairs. NEW vs R6: the elementwise phase is JOINT — all 128 threads
// of the half update 3-4 (layer,unit,batch) cells each (c-state in regs),
// after both GEMMs. Step = GEMM0||GEMM1 -> bar -> jointEW -> bar. This pools
// the FMA work (no L0/L1 imbalance), halves the EW critical path, and cuts
// 6 barrier ops/step to 2.

#define BB    2048
#define TT    1000
#define II    13
#define HH    32
#define NC    3
#define NBH   7            // batches per half
#define BPB   14           // batches per block
#define GRIDN 148
#define GSTR  9            // gate smem row stride (coprime with 32 banks)
#define NCELL (2 * HH * NBH)   // 448 cells per half

typedef unsigned long long ull;

struct alignas(16) Smem {
    float xs[2][2][NBH][16];        // [half][parity][b][k], k padded 13->16
    float h0[2][2][NBH][HH];        // [half][parity][b][k]
    float h1[2][NBH][HH];           // [half][b][k]
    float gates[2][2][128 * GSTR];  // [half][phys-group][row*GSTR + b]
};

__device__ __forceinline__ ull ffma2(ull a, ull b, ull c) {
    ull d;
    asm("fma.rn.f32x2 %0, %1, %2, %3;" : "=l"(d) : "l"(a), "l"(b), "l"(c));
    return d;
}
__device__ __forceinline__ ull packf2(float lo, float hi) {
    ull r;
    asm("mov.b64 %0, {%1, %2};" : "=l"(r) : "f"(lo), "f"(hi));
    return r;
}
__device__ __forceinline__ float hadd2(ull a) {
    float lo, hi;
    asm("mov.b64 {%0, %1}, %2;" : "=f"(lo), "=f"(hi) : "l"(a));
    return lo + hi;
}
__device__ __forceinline__ ull d2l(double d) { return __double_as_longlong(d); }

__device__ __forceinline__ float tanhap(float v) {
    float y;
    asm("tanh.approx.f32 %0, %1;" : "=f"(y) : "f"(v));
    return y;
}
__device__ __forceinline__ float sigf(float v) {
    return fmaf(tanhap(0.5f * v), 0.5f, 0.5f);
}

// acc[i][b] += sum over NC4 float4-chunks: v-pairs * w{i}-pairs (f32x2).
template <int NC4, int BSTR>
__device__ __forceinline__ void gemm2(ull (&acc)[2][NBH], const float* __restrict__ vb,
                                      const ull (&w0)[16], const ull (&w1)[16]) {
#pragma unroll
    for (int c = 0; c < NC4; c++) {
#pragma unroll
        for (int b = 0; b < NBH; b++) {
            double2 v = *reinterpret_cast<const double2*>(vb + b * BSTR + c * 4);
            ull vx = d2l(v.x), vy = d2l(v.y);
            acc[0][b] = ffma2(vx, w0[2 * c],     acc[0][b]);
            acc[0][b] = ffma2(vy, w0[2 * c + 1], acc[0][b]);
            acc[1][b] = ffma2(vx, w1[2 * c],     acc[1][b]);
            acc[1][b] = ffma2(vy, w1[2 * c + 1], acc[1][b]);
        }
    }
}

__global__ void __launch_bounds__(256, 1)
lstm_fused_kernel(const float* __restrict__ x,
                  const float* __restrict__ Wih0, const float* __restrict__ Whh0,
                  const float* __restrict__ bih0, const float* __restrict__ bhh0,
                  const float* __restrict__ Wih1, const float* __restrict__ Whh1,
                  const float* __restrict__ bih1, const float* __restrict__ bhh1,
                  const float* __restrict__ Wc1,  const float* __restrict__ bc1,
                  const float* __restrict__ Wc2,  const float* __restrict__ bc2,
                  float* __restrict__ out) {
    __shared__ Smem s;
    const int tid  = threadIdx.x;
    const int half = tid >> 7;
    const int lt   = tid & 127;
    const int grp  = lt >> 6;
    const int gl   = lt & 63;
    const bool is_l0 = ((grp ^ half) == 0);   // SMSP-balanced layer map
    const int l0grp = half;                    // physical group holding layer-0 gates
    const int bbase = blockIdx.x * BPB + half * NBH;

    // ---- zero state ----
    {
        float* zp = reinterpret_cast<float*>(&s);
        const int zn = (int)((sizeof(s.xs) + sizeof(s.h0) + sizeof(s.h1)) / 4);
        for (int i = tid; i < zn; i += 256) zp[i] = 0.0f;
    }
    // ---- stage x(0) (batch-clamped for tail blocks) ----
    for (int i = tid; i < 2 * NBH * II; i += 256) {
        int hf = i / (NBH * II), r = i % (NBH * II), b = r / II, k = r % II;
        int gb = blockIdx.x * BPB + hf * NBH + b;
        if (gb > BB - 1) gb = BB - 1;
        s.xs[hf][0][b][k] = x[(size_t)gb * TT * II + k];
    }

    // ---- register-resident weights: rows (gl, gl+64) of ONE layer ----
    ull wA[2][16], wB[2][16];
    ull biasA, biasB;
    if (is_l0) {
#pragma unroll
        for (int i = 0; i < 2; i++) {
            int r = gl + i * 64;
#pragma unroll
            for (int p = 0; p < 8; p++) {
                float lo = (2 * p     < II) ? Wih0[r * II + 2 * p]     : 0.0f;
                float hi = (2 * p + 1 < II) ? Wih0[r * II + 2 * p + 1] : 0.0f;
                wA[i][p] = packf2(lo, hi);
            }
#pragma unroll
            for (int p = 0; p < 16; p++)
                wB[i][p] = packf2(Whh0[r * HH + 2 * p], Whh0[r * HH + 2 * p + 1]);
        }
        biasA = packf2(bih0[gl] + bhh0[gl], 0.0f);
        biasB = packf2(bih0[gl + 64] + bhh0[gl + 64], 0.0f);
    } else {
#pragma unroll
        for (int i = 0; i < 2; i++) {
            int r = gl + i * 64;
#pragma unroll
            for (int p = 0; p < 16; p++) {
                wA[i][p] = packf2(Wih1[r * HH + 2 * p], Wih1[r * HH + 2 * p + 1]);
                wB[i][p] = packf2(Whh1[r * HH + 2 * p], Whh1[r * HH + 2 * p + 1]);
            }
        }
        biasA = packf2(bih1[gl] + bhh1[gl], 0.0f);
        biasB = packf2(bih1[gl + 64] + bhh1[gl + 64], 0.0f);
    }

    // ---- joint-EW cell assignment: 448 cells over 128 threads (4/4/3..) ----
    // cell c: layer = c>=224, unit = (c%224)/7, batch = (c%224)%7
    const int ncell = (lt < 64) ? 4 : 3;
    const int cb    = (lt < 64) ? lt * 4 : 256 + (lt - 64) * 3;
    bool  ce_is1[4];
    const float* ce_g[4];
    float* ce_h[4];
    float cst[4] = {0.f, 0.f, 0.f, 0.f};
#pragma unroll
    for (int i = 0; i < 4; i++) {
        int c = cb + ((i < ncell) ? i : 0);
        int l = (c >= 224) ? 1 : 0;
        int r = c - l * 224;
        int u = r / 7, b = r - u * 7;
        ce_is1[i] = (l != 0);
        ce_g[i] = &s.gates[half][l ? (1 - l0grp) : l0grp][u * GSTR + b];
        ce_h[i] = l ? &s.h1[half][b][u] : &s.h0[half][0][b][u];
    }
    const int h0par = NBH * HH;   // parity stride in floats

    float* gs = s.gates[half][grp];

    // ---- x staging slots (L0 threads): slots gl and gl+64 ----
    const int pb0 = gl >> 4,        pk0 = gl & 15;
    const int pb1 = (gl + 64) >> 4, pk1 = (gl + 64) & 15;
    const bool pv0 = (pb0 < NBH) && (pk0 < II);
    const bool pv1 = (pb1 < NBH) && (pk1 < II);
    int cb0 = bbase + pb0; if (cb0 > BB - 1) cb0 = BB - 1;
    int cb1 = bbase + pb1; if (cb1 > BB - 1) cb1 = BB - 1;
    const float* xc0 = x + (size_t)cb0 * TT * II + pk0;
    const float* xc1 = x + (size_t)cb1 * TT * II + pk1;

    const int idH = 1 + half;

    __syncthreads();

#define HBAR() asm volatile("bar.sync %0, 128;" :: "r"(idH) : "memory")

    for (int t = 0; t <= TT; t++) {
        // ================= phase G: both GEMMs concurrently =================
        float xn0 = 0.f, xn1 = 0.f;
        if (is_l0) {
            if (t < TT) {
                if (t + 1 < TT) {
                    if (pv0) xn0 = xc0[(size_t)(t + 1) * II];
                    if (pv1) xn1 = xc1[(size_t)(t + 1) * II];
                }
                const float* xsv = &s.xs[half][t & 1][0][0];
                const float* h0v = &s.h0[half][t & 1][0][0];
                ull acc[2][NBH];
#pragma unroll
                for (int b = 0; b < NBH; b++) { acc[0][b] = biasA; acc[1][b] = biasB; }
                gemm2<4, 16>(acc, xsv, wA[0], wA[1]);
                gemm2<8, HH>(acc, h0v, wB[0], wB[1]);
#pragma unroll
                for (int b = 0; b < NBH; b++) {
                    gs[gl * GSTR + b]        = hadd2(acc[0][b]);
                    gs[(gl + 64) * GSTR + b] = hadd2(acc[1][b]);
                }
            }
        } else {
            if (t > 0) {   // layer 1 processes tau = t-1
                const float* h0v = &s.h0[half][t & 1][0][0];
                const float* h1v = &s.h1[half][0][0];
                ull acc[2][NBH];
#pragma unroll
                for (int b = 0; b < NBH; b++) { acc[0][b] = biasA; acc[1][b] = biasB; }
                gemm2<8, HH>(acc, h0v, wA[0], wA[1]);
                gemm2<8, HH>(acc, h1v, wB[0], wB[1]);
#pragma unroll
                for (int b = 0; b < NBH; b++) {
                    gs[gl * GSTR + b]        = hadd2(acc[0][b]);
                    gs[(gl + 64) * GSTR + b] = hadd2(acc[1][b]);
                }
            }
        }
        HBAR();   // gates(t) ready; h0/h1/xs free to overwrite

        // ================= phase E: joint elementwise =================
#pragma unroll
        for (int i = 0; i < 4; i++) {
            if (i < ncell) {
                bool act = ce_is1[i] ? (t > 0) : (t < TT);
                if (act) {
                    const float* g = ce_g[i];
                    float gi = g[0];
                    float gf = g[32 * GSTR];
                    float gg = g[64 * GSTR];
                    float go = g[96 * GSTR];
                    float ig = sigf(gi), fg = sigf(gf);
                    float gv = tanhap(gg), og = sigf(go);
                    cst[i] = fmaf(fg, cst[i], ig * gv);
                    float hv = og * tanhap(cst[i]);
                    float* hp = ce_h[i];
                    if (!ce_is1[i]) hp += ((t + 1) & 1) * h0par;
                    *hp = hv;
                }
            }
        }
        if (is_l0 && (t + 1 < TT)) {
            if (pv0) s.xs[half][(t + 1) & 1][pb0][pk0] = xn0;
            if (pv1) s.xs[half][(t + 1) & 1][pb1][pk1] = xn1;
        }
        HBAR();   // h(t) / x(t+1) published
    }
    __syncthreads();

    // ---- classifier head ----
    {
        int hj = lt & 31, hb = lt >> 5;
        float* hs = s.gates[half][0];
#pragma unroll
        for (int s2 = 0; s2 < 2; s2++) {
            int b = hb + 4 * s2;
            if (b < NBH) {
                float a = bc1[hj];
#pragma unroll
                for (int k = 0; k < HH; k++)
                    a = fmaf(s.h1[half][b][k], Wc1[hj * HH + k], a);
                hs[hj * GSTR + b] = fmaxf(a, 0.0f);
            }
        }
    }
    __syncthreads();
    if (lt < NBH * NC) {
        int b = lt / NC, c = lt - b * NC;
        if (bbase + b < BB) {
            float* hs = s.gates[half][0];
            float o = bc2[c];
#pragma unroll
            for (int j = 0; j < HH; j++)
                o = fmaf(hs[j * GSTR + b], Wc2[c * HH + j], o);
            out[(size_t)(bbase + b) * NC + c] = o;
        }
    }
#undef HBAR
}

extern "C" void kernel_launch(void* const* d_in, const int* in_sizes, int n_in,
                              void* d_out, int out_size) {
    const float* x    = (const float*)d_in[0];
    const float* Wih0 = (const float*)d_in[1];
    const float* Whh0 = (const float*)d_in[2];
    const float* bih0 = (const float*)d_in[3];
    const float* bhh0 = (const float*)d_in[4];
    const float* Wih1 = (const float*)d_in[5];
    const float* Whh1 = (const float*)d_in[6];
    const float* bih1 = (const float*)d_in[7];
    const float* bhh1 = (const float*)d_in[8];
    const float* Wc1  = (const float*)d_in[9];
    const float* bc1  = (const float*)d_in[10];
    const float* Wc2  = (const float*)d_in[11];
    const float* bc2  = (const float*)d_in[12];
    float* out = (float*)d_out;

    lstm_fused_kernel<<<GRIDN, 256>>>(
        x, Wih0, Whh0, bih0, bhh0, Wih1, Whh1, bih1, bhh1,
        Wc1, bc1, Wc2, bc2, out);
}